// round 13
// baseline (speedup 1.0000x reference)
#include <cuda_runtime.h>
#include <cuda_fp16.h>
#include <cstdint>

#define W_g 200
#define H_g 200
#define NQ 40000
#define Dm 256
#define M_ROWS 40000

// ---------------------------------------------------------------------------
// Device scratch (no allocations allowed)
// ---------------------------------------------------------------------------
__device__ __half g_v[NQ * Dm];       // v = value @ W_v + b_v  (fp16)
__device__ float g_soaw[NQ * 192];    // cols 0..127 so, 128..191 aw (pre-softmax)
__device__ __half g_mid[NQ * Dm];     // deform output (fp16)
__device__ __half g_qcat[NQ * 512];   // [q | q+qp] fp16
__device__ __half g_wv[256 * 256];    // W_v  transposed [n][k], fp16
__device__ __half g_wsa[192 * 512];   // [W_so | W_aw] transposed [n][k], fp16
__device__ __half g_wo[256 * 256];    // W_o  transposed [n][k], fp16

__device__ __forceinline__ uint32_t smem_u32(const void* p) {
    uint32_t a;
    asm("{ .reg .u64 t; cvta.to.shared.u64 t, %1; cvt.u32.u64 %0, t; }" : "=r"(a) : "l"(p));
    return a;
}
__device__ __forceinline__ void ldmatrix_x4(uint32_t* r, uint32_t addr) {
    asm volatile("ldmatrix.sync.aligned.m8n8.x4.shared.b16 {%0,%1,%2,%3}, [%4];"
                 : "=r"(r[0]), "=r"(r[1]), "=r"(r[2]), "=r"(r[3]) : "r"(addr));
}
__device__ __forceinline__ void mma_16816(float* c, const uint32_t* a, const uint32_t* b) {
    asm volatile(
        "mma.sync.aligned.m16n8k16.row.col.f32.f16.f16.f32 "
        "{%0,%1,%2,%3}, {%4,%5,%6,%7}, {%8,%9}, {%0,%1,%2,%3};"
        : "+f"(c[0]), "+f"(c[1]), "+f"(c[2]), "+f"(c[3])
        : "r"(a[0]), "r"(a[1]), "r"(a[2]), "r"(a[3]), "r"(b[0]), "r"(b[1]));
}
__device__ __forceinline__ uint32_t pack_h2(float x, float y) {
    __half2 t = __floats2half2_rn(x, y);
    return *reinterpret_cast<uint32_t*>(&t);
}
__device__ __forceinline__ void cp_async16(uint32_t dst, const void* src) {
    asm volatile("cp.async.cg.shared.global [%0], [%1], 16;" :: "r"(dst), "l"(src));
}
#define CP_COMMIT() asm volatile("cp.async.commit_group;" ::: "memory")
template <int N> __device__ __forceinline__ void cp_wait() {
    asm volatile("cp.async.wait_group %0;" :: "n"(N) : "memory");
}

// ---------------------------------------------------------------------------
// Pure-fp16 GEMM tile, 3-stage cp.async pipeline, BK=32.
// C[m,n] = sum_k A[m,k]*Bt[n,k] + bias(n).
// Block 128x128, 8 warps (2x4), warp tile 64x32.
// smem rows 80 B (64B data + pad). 3 buffers each for A and B.
// Pipeline: issue(0),issue(1); loop c: wait<=1 -> sync -> compute(c) ->
// issue(c+2). Bufs: read c%3, pending (c+1)%3, write (c+2)%3 (distinct).
// Unconditional empty commits keep group accounting exact at the tail.
// ---------------------------------------------------------------------------
template <bool HALF_OUT>
__device__ __forceinline__ void tile_gemm(
    const __half* __restrict__ A, int ldA,
    const __half* __restrict__ B, int K, int Nb,
    const float* __restrict__ bias0, const float* __restrict__ bias1, int nsplit,
    void* __restrict__ Cv, int ldC, int bm, int bn,
    uint8_t* sA, uint8_t* sB)
{
    constexpr int TP = 128 * 80;  // 10240 B per buffer

    const int tid  = threadIdx.x;
    const int lane = tid & 31;
    const int wid  = tid >> 5;
    const int wr   = wid >> 2;
    const int wc   = wid & 3;

    float acc[4][4][4];
    #pragma unroll
    for (int i = 0; i < 4; ++i)
        #pragma unroll
        for (int j = 0; j < 4; ++j)
            #pragma unroll
            for (int k = 0; k < 4; ++k) acc[i][j][k] = 0.f;

    const int nchunk = K >> 5;

    const uint32_t sAb = smem_u32(sA);
    const uint32_t sBb = smem_u32(sB);

    // per-thread coords: 128 rows x 4 16B-chunks per tile; 2 per thread
    const int crow = tid >> 2;          // 0..63 base row (x2 via i)
    const int cg   = tid & 3;           // 16B chunk in row
    const int arow0 = min(bm + crow,      M_ROWS - 1);
    const int arow1 = min(bm + crow + 64, M_ROWS - 1);
    const int brow0 = min(bn + crow,      Nb - 1);
    const int brow1 = min(bn + crow + 64, Nb - 1);

    auto issue = [&](int c) {
        if (c < nchunk) {
            const int k0  = c << 5;
            const int buf = c % 3;
            cp_async16(sAb + buf * TP + crow * 80 + cg * 16,
                       A + (size_t)arow0 * ldA + k0 + cg * 8);
            cp_async16(sAb + buf * TP + (crow + 64) * 80 + cg * 16,
                       A + (size_t)arow1 * ldA + k0 + cg * 8);
            cp_async16(sBb + buf * TP + crow * 80 + cg * 16,
                       B + (size_t)brow0 * K + k0 + cg * 8);
            cp_async16(sBb + buf * TP + (crow + 64) * 80 + cg * 16,
                       B + (size_t)brow1 * K + k0 + cg * 8);
        }
        CP_COMMIT();   // unconditional: empty groups keep the count exact
    };

    // ldmatrix lane addressing (non-trans, validated R6-R12)
    const int a_r = (((lane >> 3) & 1) << 3) + (lane & 7);
    const int a_c = (lane >> 4) << 3;
    const int b_r = ((lane >> 4) << 3) + (lane & 7);
    const int b_c = ((lane >> 3) & 1) << 3;

    issue(0);
    issue(1);

    for (int c = 0; c < nchunk; ++c) {
        cp_wait<1>();        // oldest group (chunk c) complete
        __syncthreads();     // visible to all warps

        const int buf = c % 3;
        const uint32_t bA = sAb + buf * TP;
        const uint32_t bB = sBb + buf * TP;

        #pragma unroll
        for (int kk = 0; kk < 32; kk += 16) {
            uint32_t af[4][4];
            #pragma unroll
            for (int mc = 0; mc < 4; ++mc)
                ldmatrix_x4(af[mc], bA + (wr * 64 + mc * 16 + a_r) * 80 + (kk + a_c) * 2);
            uint32_t bf[4][2];
            #pragma unroll
            for (int jj = 0; jj < 2; ++jj) {
                uint32_t r[4];
                ldmatrix_x4(r, bB + (wc * 32 + jj * 16 + b_r) * 80 + (kk + b_c) * 2);
                bf[jj * 2 + 0][0] = r[0]; bf[jj * 2 + 0][1] = r[1];
                bf[jj * 2 + 1][0] = r[2]; bf[jj * 2 + 1][1] = r[3];
            }
            #pragma unroll
            for (int mc = 0; mc < 4; ++mc)
                #pragma unroll
                for (int ncn = 0; ncn < 4; ++ncn)
                    mma_16816(acc[mc][ncn], af[mc], bf[ncn]);
        }

        issue(c + 2);        // writes buf (c+2)%3: not read (c) nor pending (c+1)
    }

    // ---- epilogue ----
    const int gid = lane >> 2, tig = lane & 3;
    #pragma unroll
    for (int mc = 0; mc < 4; ++mc) {
        #pragma unroll
        for (int ncn = 0; ncn < 4; ++ncn) {
            const int n0 = bn + wc * 32 + ncn * 8 + tig * 2;
            if (n0 >= Nb) continue;
            const float bx = (n0     < nsplit) ? bias0[n0]     : bias1[n0 - nsplit];
            const float by = (n0 + 1 < nsplit) ? bias0[n0 + 1] : bias1[n0 + 1 - nsplit];
            const int m0 = bm + wr * 64 + mc * 16 + gid;
            if (HALF_OUT) {
                __half* C = (__half*)Cv;
                if (m0 < M_ROWS)
                    *(__half2*)&C[(size_t)m0 * ldC + n0] =
                        __floats2half2_rn(acc[mc][ncn][0] + bx, acc[mc][ncn][1] + by);
                if (m0 + 8 < M_ROWS)
                    *(__half2*)&C[(size_t)(m0 + 8) * ldC + n0] =
                        __floats2half2_rn(acc[mc][ncn][2] + bx, acc[mc][ncn][3] + by);
            } else {
                float* C = (float*)Cv;
                if (m0 < M_ROWS)
                    *(float2*)&C[(size_t)m0 * ldC + n0] =
                        make_float2(acc[mc][ncn][0] + bx, acc[mc][ncn][1] + by);
                if (m0 + 8 < M_ROWS)
                    *(float2*)&C[(size_t)(m0 + 8) * ldC + n0] =
                        make_float2(acc[mc][ncn][2] + bx, acc[mc][ncn][3] + by);
            }
        }
    }
}

// ---------------------------------------------------------------------------
// Fused G1+G2: bx<2 -> v GEMM (A=qcat cols 0..255, fp16 out),
//              bx>=2 -> soaw GEMM (A=qcat K=512, fp32 out).
// ---------------------------------------------------------------------------
__global__ __launch_bounds__(256) void gemm_g12(
    const __half* __restrict__ qcat,
    const __half* __restrict__ wv, const __half* __restrict__ wsa,
    const float* __restrict__ b_v, const float* __restrict__ b_so,
    const float* __restrict__ b_aw,
    __half* __restrict__ gv, float* __restrict__ gsoaw)
{
    extern __shared__ uint8_t smem[];
    uint8_t* sA = smem;
    uint8_t* sB = smem + 3 * 128 * 80;
    const int bx = blockIdx.x;
    const int bm = blockIdx.y * 128;
    if (bx < 2) {
        tile_gemm<true>(qcat, 512, wv, 256, 256, b_v, b_v, 256,
                        gv, 256, bm, bx * 128, sA, sB);
    } else {
        tile_gemm<false>(qcat, 512, wsa, 512, 192, b_so, b_aw, 128,
                         gsoaw, 192, bm, (bx - 2) * 128, sA, sB);
    }
}

// G3: out = mid(fp16) @ W_o + b_o (fp32 out)
__global__ __launch_bounds__(256) void gemm_g3(
    const __half* __restrict__ mid, const __half* __restrict__ wo,
    const float* __restrict__ b_o, float* __restrict__ out)
{
    extern __shared__ uint8_t smem[];
    uint8_t* sA = smem;
    uint8_t* sB = smem + 3 * 128 * 80;
    tile_gemm<false>(mid, 256, wo, 256, 256, b_o, b_o, 256,
                     out, 256, blockIdx.y * 128, blockIdx.x * 128, sA, sB);
}

// ---------------------------------------------------------------------------
// ALL conversions in one launch: qcat ([q | q+qp] fp32 -> fp16) + weight
// transposes (W[k][n] fp32 -> [n][k] fp16).
// ---------------------------------------------------------------------------
__global__ void conv_all(const float* __restrict__ q, const float* __restrict__ qp,
                         const float* __restrict__ Wv, const float* __restrict__ Wso,
                         const float* __restrict__ Waw, const float* __restrict__ Wo)
{
    const int gtid = blockIdx.x * blockDim.x + threadIdx.x;
    const int gsz  = gridDim.x * blockDim.x;

    // part 1: qcat, float4 granularity
    const int n4 = NQ * 64;
    for (int i = gtid; i < n4; i += gsz) {
        const int row = i >> 6, c4 = (i & 63) << 2;
        float4 a = *(const float4*)(q  + (size_t)row * 256 + c4);
        float4 b = *(const float4*)(qp + (size_t)row * 256 + c4);
        uint2 ha, hb;
        ha.x = pack_h2(a.x, a.y);             ha.y = pack_h2(a.z, a.w);
        hb.x = pack_h2(a.x + b.x, a.y + b.y); hb.y = pack_h2(a.z + b.z, a.w + b.w);
        *(uint2*)(g_qcat + (size_t)row * 512 + c4)       = ha;
        *(uint2*)(g_qcat + (size_t)row * 512 + 256 + c4) = hb;
    }

    // part 2: weights, scalar granularity
    const int total = 65536 + 65536 + 32768 + 65536;
    for (int i = gtid; i < total; i += gsz) {
        if (i < 65536) {
            const int k = i >> 8, n = i & 255;
            g_wv[n * 256 + k] = __float2half(Wv[i]);
        } else if (i < 131072) {
            const int j = i - 65536;
            const int k = j >> 7, n = j & 127;
            g_wsa[n * 512 + k] = __float2half(Wso[j]);
        } else if (i < 163840) {
            const int j = i - 131072;
            const int k = j >> 6, n = j & 63;
            g_wsa[(128 + n) * 512 + k] = __float2half(Waw[j]);
        } else {
            const int j = i - 163840;
            const int k = j >> 8, n = j & 255;
            g_wo[n * 256 + k] = __float2half(Wo[j]);
        }
    }
}

// ---------------------------------------------------------------------------
// Deformable sampling (R10/R12-validated: half2 gathers, fp16 mid out).
// ---------------------------------------------------------------------------
__global__ __launch_bounds__(256) void deform_kernel(
    const __half* __restrict__ v, const float* __restrict__ soaw,
    const float* __restrict__ ref, __half* __restrict__ mid)
{
    __shared__ float4 s_w[64];
    __shared__ int4   s_idx[64];

    const int q   = blockIdx.x;
    const int tid = threadIdx.x;

    if (tid < 64) {
        const int h  = tid >> 3;
        const int qq = (tid >> 2) & 1;
        const int p  = tid & 3;
        const float* srow = soaw + (size_t)q * 192;

        const float rpx = ref[q * 2 + 0];
        const float rpy = ref[q * 2 + 1];

        const float sx = srow[h * 16 + qq * 8 + p * 2 + 0];
        const float sy = srow[h * 16 + qq * 8 + p * 2 + 1];
        float a        = srow[128 + h * 8 + qq * 4 + p];

        float m = fmaxf(a, __shfl_xor_sync(0xffffffffu, a, 1));
        m = fmaxf(m, __shfl_xor_sync(0xffffffffu, m, 2));
        float e = __expf(a - m);
        float s = e + __shfl_xor_sync(0xffffffffu, e, 1);
        s = s + __shfl_xor_sync(0xffffffffu, s, 2);
        const float wt = 0.5f * e / s;

        const float x = fmaf(rpx, (float)W_g, sx) - 0.5f;
        const float y = fmaf(rpy, (float)H_g, sy) - 0.5f;
        const float x0f = floorf(x), y0f = floorf(y);
        const int   x0 = (int)x0f,  y0 = (int)y0f;
        const float wx1 = x - x0f, wx0 = 1.f - wx1;
        const float wy1 = y - y0f, wy0 = 1.f - wy1;

        const bool vx0 = (x0 >= 0) && (x0 < W_g);
        const bool vx1 = (x0 + 1 >= 0) && (x0 + 1 < W_g);
        const bool vy0 = (y0 >= 0) && (y0 < H_g);
        const bool vy1 = (y0 + 1 >= 0) && (y0 + 1 < H_g);
        const int cx0 = min(max(x0, 0),     W_g - 1);
        const int cx1 = min(max(x0 + 1, 0), W_g - 1);
        const int cy0 = min(max(y0, 0),     H_g - 1);
        const int cy1 = min(max(y0 + 1, 0), H_g - 1);

        float4 w;
        w.x = wt * wx0 * wy0 * (float)(vx0 && vy0);
        w.y = wt * wx1 * wy0 * (float)(vx1 && vy0);
        w.z = wt * wx0 * wy1 * (float)(vx0 && vy1);
        w.w = wt * wx1 * wy1 * (float)(vx1 && vy1);

        int4 ix;   // byte offsets; v row = 256 half = 512 B
        ix.x = (cy0 * W_g + cx0) * 512;
        ix.y = (cy0 * W_g + cx1) * 512;
        ix.z = (cy1 * W_g + cx0) * 512;
        ix.w = (cy1 * W_g + cx1) * 512;

        s_w[tid]   = w;
        s_idx[tid] = ix;
    }
    __syncthreads();

    const int h    = tid >> 5;
    const int lane = tid & 31;
    const int sel  = lane >> 4;          // which point of the pair
    const int ch   = (lane & 15) * 2;    // channel pair
    const char* vh = (const char*)v + (size_t)(h * 32 + ch) * 2;

    float2 acc = make_float2(0.f, 0.f);
    #pragma unroll
    for (int i = 0; i < 4; ++i) {
        const int t = h * 8 + i * 2 + sel;
        const float4 w  = s_w[t];
        const int4   ix = s_idx[t];
        float2 f;
        f = __half22float2(*(const __half2*)(vh + ix.x));
        acc.x = fmaf(w.x, f.x, acc.x); acc.y = fmaf(w.x, f.y, acc.y);
        f = __half22float2(*(const __half2*)(vh + ix.y));
        acc.x = fmaf(w.y, f.x, acc.x); acc.y = fmaf(w.y, f.y, acc.y);
        f = __half22float2(*(const __half2*)(vh + ix.z));
        acc.x = fmaf(w.z, f.x, acc.x); acc.y = fmaf(w.z, f.y, acc.y);
        f = __half22float2(*(const __half2*)(vh + ix.w));
        acc.x = fmaf(w.w, f.x, acc.x); acc.y = fmaf(w.w, f.y, acc.y);
    }
    acc.x += __shfl_xor_sync(0xffffffffu, acc.x, 16);
    acc.y += __shfl_xor_sync(0xffffffffu, acc.y, 16);

    if (lane < 16)
        *(__half2*)&mid[(size_t)q * Dm + h * 32 + ch] = __floats2half2_rn(acc.x, acc.y);
}

// ---------------------------------------------------------------------------
extern "C" void kernel_launch(void* const* d_in, const int* in_sizes, int n_in,
                              void* d_out, int out_size)
{
    const float* query     = (const float*)d_in[0];
    const float* query_pos = (const float*)d_in[1];
    const float* refpts    = (const float*)d_in[2];
    const float* W_so      = (const float*)d_in[3];
    const float* b_so      = (const float*)d_in[4];
    const float* W_aw      = (const float*)d_in[5];
    const float* b_aw      = (const float*)d_in[6];
    const float* W_v       = (const float*)d_in[7];
    const float* b_v       = (const float*)d_in[8];
    const float* W_o       = (const float*)d_in[9];
    const float* b_o       = (const float*)d_in[10];
    float* out = (float*)d_out;

    __half *gv, *gmid, *qcat, *wv, *wsa, *wo;
    float* gsoaw;
    cudaGetSymbolAddress((void**)&gv,    g_v);
    cudaGetSymbolAddress((void**)&gsoaw, g_soaw);
    cudaGetSymbolAddress((void**)&gmid,  g_mid);
    cudaGetSymbolAddress((void**)&qcat,  g_qcat);
    cudaGetSymbolAddress((void**)&wv,  g_wv);
    cudaGetSymbolAddress((void**)&wsa, g_wsa);
    cudaGetSymbolAddress((void**)&wo,  g_wo);

    constexpr int SMEM = 6 * 128 * 80;   // 61440 B (3 bufs A + 3 bufs B)
    cudaFuncSetAttribute(gemm_g12, cudaFuncAttributeMaxDynamicSharedMemorySize, SMEM);
    cudaFuncSetAttribute(gemm_g3,  cudaFuncAttributeMaxDynamicSharedMemorySize, SMEM);

    const int gm = (M_ROWS + 127) / 128;  // 313

    conv_all<<<2048, 256>>>(query, query_pos, W_v, W_so, W_aw, W_o);
    gemm_g12<<<dim3(4, gm), 256, SMEM>>>(qcat, wv, wsa, b_v, b_so, b_aw, gv, gsoaw);
    deform_kernel<<<NQ, 256>>>(gv, gsoaw, refpts, gmid);
    gemm_g3<<<dim3(2, gm), 256, SMEM>>>(gmid, wo, b_o, out);
}